// round 6
// baseline (speedup 1.0000x reference)
#include <cuda_runtime.h>
#include <cuda_bf16.h>

// Problem constants (B=256 rows, D=512 cols, row-major [B, D])
#define B_ROWS 256
#define D_COLS 512
#define CPB 8                 // columns per block
#define GRID (D_COLS / CPB)   // 64 blocks (single wave)
#define THREADS 256
#define RPT (B_ROWS / (THREADS / CPB)) // 8 rows per thread

// Scratch (no device allocation allowed)
__device__ float g_total   = 0.0f;
__device__ int   g_counter = 0;

__global__ __launch_bounds__(THREADS) void kl_fused_kernel(
    const float* __restrict__ mu, const float* __restrict__ logvar,
    float* __restrict__ out)
{
    const int tid = threadIdx.x;
    const int c   = tid & (CPB - 1);       // column within this block's group
    const int rb  = tid >> 3;              // 0..31 row base
    const int d   = blockIdx.x * CPB + c;  // global column

    // ---- Phase 1: issue all loads up-front for max MLP ----
    float mv[RPT], lvv[RPT];
    #pragma unroll
    for (int k = 0; k < RPT; k++) {
        const int i = rb + k * 32;
        mv[k]  = mu[i * D_COLS + d];
        lvv[k] = logvar[i * D_COLS + d];
    }

    // 5 fused stats: s03 = var + mu^2, s1 = 1/var, s2 = mu,
    //                s4 = mu/var,      s5 = mu^2/var
    float s03 = 0.f, s1 = 0.f, s2 = 0.f, s4 = 0.f, s5 = 0.f;
    #pragma unroll
    for (int k = 0; k < RPT; k++) {
        const float m  = mv[k];
        const float v  = __expf(lvv[k]);
        const float iv = __expf(-lvv[k]);
        s03 += v + m * m;
        s1  += iv;
        s2  += m;
        s4  += m * iv;
        s5  += m * m * iv;
    }

    // ---- Warp reduce across row-groups: lanes {c, c+8, c+16, c+24} ----
    #pragma unroll
    for (int off = 16; off >= 8; off >>= 1) {
        s03 += __shfl_down_sync(0xFFFFFFFFu, s03, off);
        s1  += __shfl_down_sync(0xFFFFFFFFu, s1,  off);
        s2  += __shfl_down_sync(0xFFFFFFFFu, s2,  off);
        s4  += __shfl_down_sync(0xFFFFFFFFu, s4,  off);
        s5  += __shfl_down_sync(0xFFFFFFFFu, s5,  off);
    }

    __shared__ float sh[5][8][CPB];   // [stat][warp][col]
    const int warp = tid >> 5;
    const int lane = tid & 31;
    if (lane < CPB) {
        sh[0][warp][lane] = s03; sh[1][warp][lane] = s1; sh[2][warp][lane] = s2;
        sh[3][warp][lane] = s4;  sh[4][warp][lane] = s5;
    }
    __syncthreads();

    // ---- Threads 0..7: combine 8 warps for one column each ----
    float blk = 0.0f;
    if (tid < CPB) {
        float t03 = 0.f, t1 = 0.f, t2 = 0.f, t4 = 0.f, t5 = 0.f;
        #pragma unroll
        for (int w = 0; w < 8; w++) {
            t03 += sh[0][w][tid]; t1 += sh[1][w][tid]; t2 += sh[2][w][tid];
            t4  += sh[3][w][tid]; t5 += sh[4][w][tid];
        }
        const float Bf = (float)B_ROWS;
        // c_d = S_inv*(S_var + S_mu2) - 2*S_mu*S_muinv + B*S_mu2inv - B^2
        blk = t1 * t03 - 2.0f * t2 * t4 + Bf * t5 - Bf * Bf;
    }

    // ---- Tail: one REDG per block, acq_rel counter, last block finishes ----
    if (warp == 0) {
        // 8 column contributions -> one block scalar in lane 0
        blk += __shfl_down_sync(0xFFFFFFFFu, blk, 4);
        blk += __shfl_down_sync(0xFFFFFFFFu, blk, 2);
        blk += __shfl_down_sync(0xFFFFFFFFu, blk, 1);

        if (lane == 0) {
            // Fire-and-forget accumulate (relaxed; ordered by the release below)
            asm volatile("red.relaxed.gpu.global.add.f32 [%0], %1;"
                         :: "l"(&g_total), "f"(blk) : "memory");

            // acq_rel counter: release publishes my red; acquire (for the
            // last arriver) makes ALL blocks' reds visible.
            int prev;
            asm volatile("atom.acq_rel.gpu.global.add.u32 %0, [%1], 1;"
                         : "=r"(prev) : "l"(&g_counter) : "memory");

            if (prev == GRID - 1) {
                float tot;
                asm volatile("ld.acquire.gpu.global.f32 %0, [%1];"
                             : "=f"(tot) : "l"(&g_total) : "memory");
                out[0] = tot * (0.5f / (float)B_ROWS);
                // Reset scratch for next graph replay (ordered by launch boundary)
                g_total   = 0.0f;
                g_counter = 0;
            }
        }
    }
}

extern "C" void kernel_launch(void* const* d_in, const int* in_sizes, int n_in,
                              void* d_out, int out_size)
{
    const float* mu = (const float*)d_in[0];
    const float* lv = (const float*)d_in[1];
    float* out = (float*)d_out;

    kl_fused_kernel<<<GRID, THREADS>>>(mu, lv, out);
}

// round 8
// speedup vs baseline: 3.8894x; 3.8894x over previous
#include <cuda_runtime.h>
#include <cuda_bf16.h>

// Problem constants (B=256 rows, D=512 cols, row-major [B, D])
#define B_ROWS 256
#define D_COLS 512
#define CPB 8                 // columns per block
#define GRID (D_COLS / CPB)   // 64 blocks (single wave)
#define THREADS 256
#define RPT (B_ROWS / (THREADS / CPB)) // 8 rows per thread

// Scratch (no device allocation allowed)
__device__ float g_block_sum[GRID];
__device__ int   g_counter = 0;

__global__ __launch_bounds__(THREADS) void kl_fused_kernel(
    const float* __restrict__ mu, const float* __restrict__ logvar,
    float* __restrict__ out)
{
    const int tid = threadIdx.x;
    const int c   = tid & (CPB - 1);       // column within this block's group
    const int rb  = tid >> 3;              // 0..31 row base
    const int d   = blockIdx.x * CPB + c;  // global column

    // ---- Phase 1: issue all loads up-front for max MLP ----
    float mv[RPT], lvv[RPT];
    #pragma unroll
    for (int k = 0; k < RPT; k++) {
        const int i = rb + k * 32;
        mv[k]  = mu[i * D_COLS + d];
        lvv[k] = logvar[i * D_COLS + d];
    }

    // 5 fused stats: s03 = var + mu^2, s1 = 1/var, s2 = mu,
    //                s4 = mu/var,      s5 = mu^2/var
    float s03 = 0.f, s1 = 0.f, s2 = 0.f, s4 = 0.f, s5 = 0.f;
    #pragma unroll
    for (int k = 0; k < RPT; k++) {
        const float m  = mv[k];
        const float v  = __expf(lvv[k]);
        const float iv = __expf(-lvv[k]);
        s03 += v + m * m;
        s1  += iv;
        s2  += m;
        s4  += m * iv;
        s5  += m * m * iv;
    }

    // ---- Warp reduce across row-groups: lanes {c, c+8, c+16, c+24} ----
    #pragma unroll
    for (int off = 16; off >= 8; off >>= 1) {
        s03 += __shfl_down_sync(0xFFFFFFFFu, s03, off);
        s1  += __shfl_down_sync(0xFFFFFFFFu, s1,  off);
        s2  += __shfl_down_sync(0xFFFFFFFFu, s2,  off);
        s4  += __shfl_down_sync(0xFFFFFFFFu, s4,  off);
        s5  += __shfl_down_sync(0xFFFFFFFFu, s5,  off);
    }

    __shared__ float sh[5][8][CPB];   // [stat][warp][col]
    const int warp = tid >> 5;
    const int lane = tid & 31;
    if (lane < CPB) {
        sh[0][warp][lane] = s03; sh[1][warp][lane] = s1; sh[2][warp][lane] = s2;
        sh[3][warp][lane] = s4;  sh[4][warp][lane] = s5;
    }
    __syncthreads();

    // ---- Threads 0..7: combine 8 warps for one column each ----
    float blk = 0.0f;
    if (tid < CPB) {
        float t03 = 0.f, t1 = 0.f, t2 = 0.f, t4 = 0.f, t5 = 0.f;
        #pragma unroll
        for (int w = 0; w < 8; w++) {
            t03 += sh[0][w][tid]; t1 += sh[1][w][tid]; t2 += sh[2][w][tid];
            t4  += sh[3][w][tid]; t5 += sh[4][w][tid];
        }
        const float Bf = (float)B_ROWS;
        // c_d = S_inv*(S_var + S_mu2) - 2*S_mu*S_muinv + B*S_mu2inv - B^2
        blk = t1 * t03 - 2.0f * t2 * t4 + Bf * t5 - Bf * Bf;
    }
    // 8 column contributions -> one block scalar (lanes 0..7 of warp 0)
    if (warp == 0) {
        blk += __shfl_down_sync(0xFFFFFFFFu, blk, 4);
        blk += __shfl_down_sync(0xFFFFFFFFu, blk, 2);
        blk += __shfl_down_sync(0xFFFFFFFFu, blk, 1);
        if (lane == 0) g_block_sum[blockIdx.x] = blk;
    }

    // ---- Last-block final reduce (64 partials, one warp) ----
    __shared__ int is_last;
    __threadfence();
    __syncthreads();
    if (tid == 0) {
        int prev = atomicAdd(&g_counter, 1);
        is_last = (prev == GRID - 1);
    }
    __syncthreads();

    if (is_last && tid < 32) {
        float x = __ldcg(&g_block_sum[tid]) + __ldcg(&g_block_sum[tid + 32]);
        #pragma unroll
        for (int off = 16; off > 0; off >>= 1)
            x += __shfl_down_sync(0xFFFFFFFFu, x, off);
        if (tid == 0) {
            out[0] = x * (0.5f / (float)B_ROWS);
            g_counter = 0;  // reset for next graph replay
        }
    }
}

extern "C" void kernel_launch(void* const* d_in, const int* in_sizes, int n_in,
                              void* d_out, int out_size)
{
    const float* mu = (const float*)d_in[0];
    const float* lv = (const float*)d_in[1];
    float* out = (float*)d_out;

    kl_fused_kernel<<<GRID, THREADS>>>(mu, lv, out);
}